// round 2
// baseline (speedup 1.0000x reference)
#include <cuda_runtime.h>
#include <math_constants.h>

// Problem constants
#define C_IN  64
#define F_OUT 128
#define NPOS  9
#define KTOT  (NPOS * C_IN)      // 576
#define HH    128
#define WW    128
#define NB    16

// Scratch for the effective ternary weights AW (3,3,64,128) flat = (576,128)
__device__ float g_AW[KTOT * F_OUT];

// ---------------------------------------------------------------------------
// Kernel 1: compute AW = top4_mask(D + gumbel) * sign(kern)
// One thread per (f, c) pair: 128*64 = 8192 threads.
// logits reshape (3,3,64,128)->(128,64,9) is a flat reinterpret, so the 9
// values for pair t live at flat offsets [t*9, t*9+9) of D / gumbel_u, and the
// mask applies at the SAME flat offsets of kern -> AW.
// ---------------------------------------------------------------------------
__global__ void weights_kernel(const float* __restrict__ D,
                               const float* __restrict__ u,
                               const float* __restrict__ kern) {
    int t = blockIdx.x * blockDim.x + threadIdx.x;
    if (t >= F_OUT * C_IN) return;

    const float* Dp = D + t * NPOS;
    const float* up = u + t * NPOS;

    float pert[NPOS];
#pragma unroll
    for (int n = 0; n < NPOS; ++n) {
        float g = -0.001f * logf(-logf(up[n] + 1e-20f) + 1e-20f);
        pert[n] = Dp[n] + g;
    }

    // top-4 by value (values are continuous; ties have measure zero)
    unsigned sel = 0;
#pragma unroll
    for (int j = 0; j < 4; ++j) {
        int   bi = 0;
        float bv = -CUDART_INF_F;
#pragma unroll
        for (int n = 0; n < NPOS; ++n) {
            bool taken = (sel >> n) & 1u;
            if (!taken && pert[n] > bv) { bv = pert[n]; bi = n; }
        }
        sel |= (1u << bi);
    }

    const float* kp = kern + t * NPOS;
    float*       op = g_AW + t * NPOS;
#pragma unroll
    for (int n = 0; n < NPOS; ++n) {
        float w = kp[n];
        float s = (w > 0.f) ? 1.f : ((w < 0.f) ? -1.f : 0.f);
        op[n] = ((sel >> n) & 1u) ? s : 0.f;
    }
}

// ---------------------------------------------------------------------------
// Kernel 2: implicit-GEMM 3x3 SAME conv, NHWC.
// C[M=262144, 128] = Xpatch[M, 576] * g_AW[576, 128], +bias, ReLU.
// Tile: BM=64 pixels (contiguous along w), BN=128 (all f), BK=64 (= C_IN of
// one kernel position). 256 threads, each computes a 4(m) x 8(n) register tile.
// ---------------------------------------------------------------------------
__global__ __launch_bounds__(256)
void conv_kernel(const float* __restrict__ x,
                 const float* __restrict__ bias,
                 float* __restrict__ out) {
    __shared__ float  As[64][64];   // [ci][tw]  (transposed A tile)
    __shared__ float4 Ws[64][32];   // [k][f/4]  (64 x 128 weight tile)

    const int tid  = threadIdx.x;
    const int pix0 = blockIdx.x << 6;             // 64 pixels per CTA
    const int n    = pix0 >> 14;                  // / (128*128)
    const int h    = (pix0 >> 7) & 127;
    const int w0   = pix0 & 127;                  // 0 or 64

    const int tm0 = (tid & 15) << 2;              // 0..60, step 4
    const int tn4 = (tid >> 4) << 1;              // float4 col index, tn0 = tn4*4

    float acc[4][8];
#pragma unroll
    for (int i = 0; i < 4; ++i)
#pragma unroll
        for (int j = 0; j < 8; ++j) acc[i][j] = 0.f;

    const int ltw  = tid & 63;                    // loader pixel-in-tile
    const int lci0 = tid >> 6;                    // loader ci4 base (0..3)

#pragma unroll 1
    for (int kpos = 0; kpos < NPOS; ++kpos) {
        const int  dh = kpos / 3 - 1;
        const int  dw = kpos % 3 - 1;
        const int  hh = h + dh;
        const int  ww = w0 + ltw + dw;
        const bool ok = ((unsigned)hh < 128u) && ((unsigned)ww < 128u);
        const float* src = x + (((long)n * HH + hh) * WW + ww) * C_IN;

        // A tile: 64 pixels x 64 channels; store transposed [ci][tw]
#pragma unroll
        for (int i = 0; i < 4; ++i) {
            int ci = (lci0 + 4 * i) << 2;         // 0..60 step 4
            float4 v = make_float4(0.f, 0.f, 0.f, 0.f);
            if (ok) v = *reinterpret_cast<const float4*>(src + ci);
            As[ci + 0][ltw] = v.x;
            As[ci + 1][ltw] = v.y;
            As[ci + 2][ltw] = v.z;
            As[ci + 3][ltw] = v.w;
        }

        // W tile: rows [kpos*64, kpos*64+64) of g_AW, fully coalesced
        const float4* Wg = reinterpret_cast<const float4*>(g_AW + kpos * (C_IN * F_OUT));
#pragma unroll
        for (int i = 0; i < 8; ++i) {
            int s = tid + (i << 8);               // 0..2047
            Ws[s >> 5][s & 31] = Wg[s];
        }
        __syncthreads();

#pragma unroll 16
        for (int k = 0; k < 64; ++k) {
            float4 a  = *reinterpret_cast<const float4*>(&As[k][tm0]);
            float4 b0 = Ws[k][tn4];
            float4 b1 = Ws[k][tn4 + 1];
            float av[4] = {a.x, a.y, a.z, a.w};
            float bv[8] = {b0.x, b0.y, b0.z, b0.w, b1.x, b1.y, b1.z, b1.w};
#pragma unroll
            for (int i = 0; i < 4; ++i)
#pragma unroll
                for (int j = 0; j < 8; ++j)
                    acc[i][j] = fmaf(av[i], bv[j], acc[i][j]);
        }
        __syncthreads();
    }

    // Epilogue: + bias, ReLU, write out[pixel][f]
    const int tn0 = tn4 << 2;
    float bb[8];
#pragma unroll
    for (int j = 0; j < 8; ++j) bb[j] = bias[tn0 + j];

#pragma unroll
    for (int i = 0; i < 4; ++i) {
        float4 o0, o1;
        o0.x = fmaxf(acc[i][0] + bb[0], 0.f);
        o0.y = fmaxf(acc[i][1] + bb[1], 0.f);
        o0.z = fmaxf(acc[i][2] + bb[2], 0.f);
        o0.w = fmaxf(acc[i][3] + bb[3], 0.f);
        o1.x = fmaxf(acc[i][4] + bb[4], 0.f);
        o1.y = fmaxf(acc[i][5] + bb[5], 0.f);
        o1.z = fmaxf(acc[i][6] + bb[6], 0.f);
        o1.w = fmaxf(acc[i][7] + bb[7], 0.f);
        float* dst = out + (long)(pix0 + tm0 + i) * F_OUT + tn0;
        *reinterpret_cast<float4*>(dst)     = o0;
        *reinterpret_cast<float4*>(dst + 4) = o1;
    }
}

// ---------------------------------------------------------------------------
// Launch: inputs per metadata order: x, kern, b, D, gumbel_u
// ---------------------------------------------------------------------------
extern "C" void kernel_launch(void* const* d_in, const int* in_sizes, int n_in,
                              void* d_out, int out_size) {
    const float* x    = (const float*)d_in[0];
    const float* kern = (const float*)d_in[1];
    const float* b    = (const float*)d_in[2];
    const float* D    = (const float*)d_in[3];
    const float* u    = (const float*)d_in[4];
    float* out = (float*)d_out;

    weights_kernel<<<(F_OUT * C_IN + 255) / 256, 256>>>(D, u, kern);

    const int m_tiles = (NB * HH * WW) / 64;      // 4096
    conv_kernel<<<m_tiles, 256>>>(x, b, out);
}

// round 4
// speedup vs baseline: 2.9623x; 2.9623x over previous
#include <cuda_runtime.h>
#include <cuda_bf16.h>
#include <math_constants.h>
#include <cstdint>
#include <cstddef>

#define C_IN  64
#define F_OUT 128
#define NPOS  9
#define HH    128
#define WWID  128
#define NB    16
#define NPIX  (NB*HH*WWID)

__device__ __nv_bfloat16 g_xhi[(size_t)NPIX * C_IN];
__device__ __nv_bfloat16 g_xlo[(size_t)NPIX * C_IN];
__device__ __nv_bfloat16 g_W[NPOS * F_OUT * C_IN];   // [kpos][f][c]

// ---------------- kernel 1: ternary weights ----------------
__global__ void weights_kernel(const float* __restrict__ D,
                               const float* __restrict__ u,
                               const float* __restrict__ kern) {
    int t = blockIdx.x * blockDim.x + threadIdx.x;
    if (t >= F_OUT * C_IN) return;
    const float* Dp = D + t * NPOS;
    const float* up = u + t * NPOS;
    float pert[NPOS];
#pragma unroll
    for (int n = 0; n < NPOS; ++n) {
        float g = -0.001f * logf(-logf(up[n] + 1e-20f) + 1e-20f);
        pert[n] = Dp[n] + g;
    }
    unsigned sel = 0;
#pragma unroll
    for (int j = 0; j < 4; ++j) {
        int bi = 0; float bv = -CUDART_INF_F;
#pragma unroll
        for (int n = 0; n < NPOS; ++n) {
            bool tk = (sel >> n) & 1u;
            if (!tk && pert[n] > bv) { bv = pert[n]; bi = n; }
        }
        sel |= (1u << bi);
    }
    const float* kp = kern + t * NPOS;
#pragma unroll
    for (int n = 0; n < NPOS; ++n) {
        int p = t * NPOS + n;                    // flat index in (3,3,64,128)
        float w = kp[n];
        float s = (w > 0.f) ? 1.f : ((w < 0.f) ? -1.f : 0.f);
        float v = ((sel >> n) & 1u) ? s : 0.f;
        int f = p & 127, c = (p >> 7) & 63, kpos = p >> 13;
        g_W[kpos * 8192 + f * 64 + c] = __float2bfloat16_rn(v);
    }
}

// ---------------- kernel 2: x -> bf16 hi/lo ----------------
__global__ void convert_kernel(const float* __restrict__ x) {
    size_t i = (size_t)blockIdx.x * blockDim.x + threadIdx.x;  // float4 groups
    float4 v = reinterpret_cast<const float4*>(x)[i];
    float vv[4] = {v.x, v.y, v.z, v.w};
    unsigned h[4], l[4];
#pragma unroll
    for (int j = 0; j < 4; ++j) {
        __nv_bfloat16 hb = __float2bfloat16_rn(vv[j]);
        __nv_bfloat16 lb = __float2bfloat16_rn(vv[j] - __bfloat162float(hb));
        h[j] = __bfloat16_as_ushort(hb); l[j] = __bfloat16_as_ushort(lb);
    }
    uint2 ph = make_uint2(h[0] | (h[1] << 16), h[2] | (h[3] << 16));
    uint2 pl = make_uint2(l[0] | (l[1] << 16), l[2] | (l[3] << 16));
    reinterpret_cast<uint2*>(g_xhi)[i] = ph;
    reinterpret_cast<uint2*>(g_xlo)[i] = pl;
}

// ---------------- helpers ----------------
__device__ __forceinline__ uint32_t s2u(const void* p) {
    uint32_t a;
    asm("{ .reg .u64 t; cvta.to.shared.u64 t, %1; cvt.u32.u64 %0, t; }"
        : "=r"(a) : "l"(p));
    return a;
}
__device__ __forceinline__ void cpa16z(uint32_t dst, const void* src, uint32_t nbytes) {
    asm volatile("cp.async.cg.shared.global [%0], [%1], 16, %2;"
                 :: "r"(dst), "l"(src), "r"(nbytes) : "memory");
}
__device__ __forceinline__ void cpa4(uint32_t dst, const void* src) {
    asm volatile("cp.async.ca.shared.global [%0], [%1], 4;"
                 :: "r"(dst), "l"(src) : "memory");
}
#define CP_COMMIT() asm volatile("cp.async.commit_group;" ::: "memory")
#define CP_WAIT1()  asm volatile("cp.async.wait_group 1;" ::: "memory")

__device__ __forceinline__ void ldsm4(uint32_t* r, uint32_t addr) {
    asm volatile("ldmatrix.sync.aligned.m8n8.x4.shared.b16 {%0,%1,%2,%3}, [%4];"
                 : "=r"(r[0]), "=r"(r[1]), "=r"(r[2]), "=r"(r[3]) : "r"(addr));
}
__device__ __forceinline__ void mma16816(float* d, const uint32_t* a,
                                         uint32_t b0, uint32_t b1) {
    asm volatile(
        "mma.sync.aligned.m16n8k16.row.col.f32.bf16.bf16.f32 "
        "{%0,%1,%2,%3}, {%4,%5,%6,%7}, {%8,%9}, {%0,%1,%2,%3};"
        : "+f"(d[0]), "+f"(d[1]), "+f"(d[2]), "+f"(d[3])
        : "r"(a[0]), "r"(a[1]), "r"(a[2]), "r"(a[3]), "r"(b0), "r"(b1));
}

// smem layout (dynamic)
#define A_STRIDE  144                       // bytes per A row (72 bf16, padded)
#define A_BUF     (128 * A_STRIDE)          // 18432
#define B_PAD     132                       // u32 stride of Ws rows
#define B_BUF     (32 * B_PAD * 4)          // 16896
#define SM_BOFF   (2 * A_BUF)               // 36864
#define SMEM_SZ   (SM_BOFF + 2 * B_BUF)     // 70656

__device__ __forceinline__ void loadA(uint32_t abase, const __nv_bfloat16* arr,
                                      int h, int kpos, int tid) {
    const int dh = kpos / 3 - 1, dw = kpos % 3 - 1;
    const int hin = h + dh;
    const bool hok = (unsigned)hin < 128u;
    const __nv_bfloat16* rowp = arr + (size_t)hin * (WWID * C_IN);
#pragma unroll
    for (int i = 0; i < 4; ++i) {
        int idx = i * 256 + tid;
        int r = idx >> 3, c16 = idx & 7;
        int win = r + dw;
        bool ok = hok && ((unsigned)win < 128u);
        const void* src = ok ? (const void*)(rowp + win * C_IN + c16 * 8)
                             : (const void*)arr;
        cpa16z(abase + r * A_STRIDE + c16 * 16, src, ok ? 16u : 0u);
    }
}
__device__ __forceinline__ void loadB(uint32_t bbase, int kpos, int tid) {
    const uint32_t* w = reinterpret_cast<const uint32_t*>(g_W) + kpos * 4096;
#pragma unroll
    for (int i = 0; i < 16; ++i) {
        int idx = i * 256 + tid;
        int c2 = idx & 31, f = idx >> 5;            // coalesced global read
        cpa4(bbase + (c2 * B_PAD + f) * 4, w + f * 32 + c2);
    }
}

// ---------------- kernel 3: mma.sync conv ----------------
__global__ void __launch_bounds__(256)
conv_mma_kernel(const float* __restrict__ bias, float* __restrict__ out) {
    extern __shared__ char smem[];
    const uint32_t sb = s2u(smem);
    const int tid = threadIdx.x, wid = tid >> 5, l = tid & 31;
    const int m0w = (wid & 1) * 64, n0w = (wid >> 1) * 32;
    const int bx = blockIdx.x;
    const int n = bx >> 7, h = bx & 127;

    const __nv_bfloat16* xhi = g_xhi + (size_t)n * (HH * WWID * C_IN);
    const __nv_bfloat16* xlo = g_xlo + (size_t)n * (HH * WWID * C_IN);

    float acc[4][4][4];
#pragma unroll
    for (int mi = 0; mi < 4; ++mi)
#pragma unroll
        for (int ni = 0; ni < 4; ++ni)
#pragma unroll
            for (int c = 0; c < 4; ++c) acc[mi][ni][c] = 0.f;

    // prologue: stage 0 (A hi kpos0) + B kpos0
    loadA(sb, xhi, h, 0, tid);
    loadB(sb + SM_BOFF, 0, tid);
    CP_COMMIT();

    // per-lane ldmatrix address pieces
    const uint32_t arow = (uint32_t)(m0w + (l & 15)) * A_STRIDE + (l >> 4) * 16;

#pragma unroll 1
    for (int s = 0; s < 18; ++s) {
        if (s < 17) {
            const int s1 = s + 1, k1 = s1 >> 1;
            loadA(sb + (s1 & 1) * A_BUF, (s1 & 1) ? xlo : xhi, h, k1, tid);
            if ((s1 & 1) == 0) loadB(sb + SM_BOFF + (k1 & 1) * B_BUF, k1, tid);
        }
        CP_COMMIT();
        CP_WAIT1();
        __syncthreads();

        const uint32_t abase = sb + (s & 1) * A_BUF;
        const uint32_t* Ws = reinterpret_cast<const uint32_t*>(
            smem + SM_BOFF + ((s >> 1) & 1) * B_BUF);

#pragma unroll
        for (int ks = 0; ks < 4; ++ks) {
            uint32_t a[4][4];
#pragma unroll
            for (int mi = 0; mi < 4; ++mi)
                ldsm4(a[mi], abase + arow + mi * 16 * A_STRIDE + ks * 32);
            uint32_t b0[4], b1[4];
#pragma unroll
            for (int ni = 0; ni < 4; ++ni) {
                int nidx = n0w + ni * 8 + (l >> 2);
                b0[ni] = Ws[(ks * 8 + (l & 3)) * B_PAD + nidx];
                b1[ni] = Ws[(ks * 8 + (l & 3) + 4) * B_PAD + nidx];
            }
#pragma unroll
            for (int mi = 0; mi < 4; ++mi)
#pragma unroll
                for (int ni = 0; ni < 4; ++ni)
                    mma16816(acc[mi][ni], a[mi], b0[ni], b1[ni]);
        }
        __syncthreads();
    }

    // epilogue: +bias, ReLU, store
    float2 bb[4];
#pragma unroll
    for (int ni = 0; ni < 4; ++ni) {
        int col = n0w + ni * 8 + (l & 3) * 2;
        bb[ni] = *reinterpret_cast<const float2*>(bias + col);
    }
#pragma unroll
    for (int mi = 0; mi < 4; ++mi) {
#pragma unroll
        for (int ni = 0; ni < 4; ++ni) {
            int col = n0w + ni * 8 + (l & 3) * 2;
            size_t pix = (size_t)bx * 128 + m0w + mi * 16 + (l >> 2);
            float2 o0, o1;
            o0.x = fmaxf(acc[mi][ni][0] + bb[ni].x, 0.f);
            o0.y = fmaxf(acc[mi][ni][1] + bb[ni].y, 0.f);
            o1.x = fmaxf(acc[mi][ni][2] + bb[ni].x, 0.f);
            o1.y = fmaxf(acc[mi][ni][3] + bb[ni].y, 0.f);
            *reinterpret_cast<float2*>(out + pix * F_OUT + col) = o0;
            *reinterpret_cast<float2*>(out + (pix + 8) * F_OUT + col) = o1;
        }
    }
}

// ---------------- launch ----------------
extern "C" void kernel_launch(void* const* d_in, const int* in_sizes, int n_in,
                              void* d_out, int out_size) {
    const float* x    = (const float*)d_in[0];
    const float* kern = (const float*)d_in[1];
    const float* b    = (const float*)d_in[2];
    const float* D    = (const float*)d_in[3];
    const float* u    = (const float*)d_in[4];
    float* out = (float*)d_out;

    static int smem_set = 0;
    if (!smem_set) {
        cudaFuncSetAttribute(conv_mma_kernel,
                             cudaFuncAttributeMaxDynamicSharedMemorySize, SMEM_SZ);
        smem_set = 1;
    }

    weights_kernel<<<(F_OUT * C_IN + 255) / 256, 256>>>(D, u, kern);
    convert_kernel<<<(NPIX * C_IN / 4) / 256, 256>>>(x);
    conv_mma_kernel<<<NB * HH, 256, SMEM_SZ>>>(b, out);
}

// round 5
// speedup vs baseline: 4.2280x; 1.4273x over previous
#include <cuda_runtime.h>
#include <cuda_bf16.h>
#include <math_constants.h>
#include <cstdint>
#include <cstddef>

#define C_IN  64
#define F_OUT 128
#define NPOS  9
#define HH    128
#define WWID  128
#define NB    16
#define NPIX  (NB*HH*WWID)

__device__ __nv_bfloat16 g_xhi[(size_t)NPIX * C_IN];
__device__ __nv_bfloat16 g_xlo[(size_t)NPIX * C_IN];
__device__ __nv_bfloat16 g_W[NPOS * F_OUT * C_IN];   // [kpos][f][c]

// ---------------- kernel 1: ternary weights ----------------
__global__ void weights_kernel(const float* __restrict__ D,
                               const float* __restrict__ u,
                               const float* __restrict__ kern) {
    int t = blockIdx.x * blockDim.x + threadIdx.x;
    if (t >= F_OUT * C_IN) return;
    const float* Dp = D + t * NPOS;
    const float* up = u + t * NPOS;
    float pert[NPOS];
#pragma unroll
    for (int n = 0; n < NPOS; ++n) {
        float g = -0.001f * logf(-logf(up[n] + 1e-20f) + 1e-20f);
        pert[n] = Dp[n] + g;
    }
    unsigned sel = 0;
#pragma unroll
    for (int j = 0; j < 4; ++j) {
        int bi = 0; float bv = -CUDART_INF_F;
#pragma unroll
        for (int n = 0; n < NPOS; ++n) {
            bool tk = (sel >> n) & 1u;
            if (!tk && pert[n] > bv) { bv = pert[n]; bi = n; }
        }
        sel |= (1u << bi);
    }
    const float* kp = kern + t * NPOS;
#pragma unroll
    for (int n = 0; n < NPOS; ++n) {
        int p = t * NPOS + n;                    // flat index in (3,3,64,128)
        float w = kp[n];
        float s = (w > 0.f) ? 1.f : ((w < 0.f) ? -1.f : 0.f);
        float v = ((sel >> n) & 1u) ? s : 0.f;
        int f = p & 127, c = (p >> 7) & 63, kpos = p >> 13;
        g_W[kpos * 8192 + f * 64 + c] = __float2bfloat16_rn(v);
    }
}

// ---------------- kernel 2: x -> bf16 hi/lo ----------------
__global__ void convert_kernel(const float* __restrict__ x) {
    size_t i = (size_t)blockIdx.x * blockDim.x + threadIdx.x;  // float4 groups
    float4 v = reinterpret_cast<const float4*>(x)[i];
    float vv[4] = {v.x, v.y, v.z, v.w};
    unsigned h[4], l[4];
#pragma unroll
    for (int j = 0; j < 4; ++j) {
        __nv_bfloat16 hb = __float2bfloat16_rn(vv[j]);
        __nv_bfloat16 lb = __float2bfloat16_rn(vv[j] - __bfloat162float(hb));
        h[j] = __bfloat16_as_ushort(hb); l[j] = __bfloat16_as_ushort(lb);
    }
    uint2 ph = make_uint2(h[0] | (h[1] << 16), h[2] | (h[3] << 16));
    uint2 pl = make_uint2(l[0] | (l[1] << 16), l[2] | (l[3] << 16));
    reinterpret_cast<uint2*>(g_xhi)[i] = ph;
    reinterpret_cast<uint2*>(g_xlo)[i] = pl;
}

// ---------------- helpers ----------------
__device__ __forceinline__ uint32_t s2u(const void* p) {
    uint32_t a;
    asm("{ .reg .u64 t; cvta.to.shared.u64 t, %1; cvt.u32.u64 %0, t; }"
        : "=r"(a) : "l"(p));
    return a;
}
__device__ __forceinline__ void cpa16(uint32_t dst, const void* src) {
    asm volatile("cp.async.cg.shared.global [%0], [%1], 16;"
                 :: "r"(dst), "l"(src) : "memory");
}
#define CP_COMMIT() asm volatile("cp.async.commit_group;" ::: "memory")
#define CP_WAIT1()  asm volatile("cp.async.wait_group 1;" ::: "memory")

__device__ __forceinline__ void ldsm4(uint32_t* r, uint32_t addr) {
    asm volatile("ldmatrix.sync.aligned.m8n8.x4.shared.b16 {%0,%1,%2,%3}, [%4];"
                 : "=r"(r[0]), "=r"(r[1]), "=r"(r[2]), "=r"(r[3]) : "r"(addr));
}
__device__ __forceinline__ void mma16816(float* d, const uint32_t* a,
                                         uint32_t b0, uint32_t b1) {
    asm volatile(
        "mma.sync.aligned.m16n8k16.row.col.f32.bf16.bf16.f32 "
        "{%0,%1,%2,%3}, {%4,%5,%6,%7}, {%8,%9}, {%0,%1,%2,%3};"
        : "+f"(d[0]), "+f"(d[1]), "+f"(d[2]), "+f"(d[3])
        : "r"(a[0]), "r"(a[1]), "r"(a[2]), "r"(a[3]), "r"(b0), "r"(b1));
}

// smem layout
#define A_STRIDE 144                    // bytes per A row (64 bf16 + 16B pad)
#define A_ROWS   130                    // w_in -1..128 (rows 0,129 zero)
#define A_BUF    (A_ROWS * A_STRIDE)    // 18720
#define B_STRIDE 144
#define B_BUF    (128 * B_STRIDE)       // 18432
#define SM_BOFF  (4 * A_BUF)            // 74880
#define SMEM_SZ  (SM_BOFF + 2 * B_BUF)  // 111744

// Load A tile for (array, dh): rows 1..128 <- w_in 0..127; rows 0,129 zeroed.
__device__ __forceinline__ void loadA(uint32_t abase, const __nv_bfloat16* arr,
                                      int h, int dh, int tid) {
    const int hin = h + dh;
    if ((unsigned)hin < 128u) {
        // zero pad rows 0 and 129 (288 B = 18 x 16B)
        if (tid < 18) {
            uint32_t adr = abase + ((tid < 9) ? 0u : (uint32_t)(129 * A_STRIDE))
                         + (uint32_t)(tid % 9) * 16u;
            asm volatile("st.shared.v4.b32 [%0], {%1,%1,%1,%1};"
                         :: "r"(adr), "r"(0) : "memory");
        }
        const __nv_bfloat16* rowp = arr + (size_t)hin * (WWID * C_IN);
#pragma unroll
        for (int i = 0; i < 4; ++i) {
            int idx = i * 256 + tid;           // 0..1023
            int r = idx >> 3, c16 = idx & 7;   // r = w_in, 8 x 16B per row
            cpa16(abase + (uint32_t)(r + 1) * A_STRIDE + c16 * 16,
                  rowp + r * C_IN + c16 * 8);
        }
    } else {
        // whole tile zero (1170 x 16B)
#pragma unroll
        for (int i = 0; i < 5; ++i) {
            int idx = i * 256 + tid;
            if (idx < (A_BUF / 16))
                asm volatile("st.shared.v4.b32 [%0], {%1,%1,%1,%1};"
                             :: "r"(abase + idx * 16), "r"(0) : "memory");
        }
    }
}
__device__ __forceinline__ void loadB(uint32_t bbase, int kpos, int tid) {
    const __nv_bfloat16* w = g_W + kpos * 8192;
#pragma unroll
    for (int i = 0; i < 4; ++i) {
        int idx = i * 256 + tid;               // 0..1023
        int f = idx >> 3, c16 = idx & 7;
        cpa16(bbase + (uint32_t)f * B_STRIDE + c16 * 16, w + f * 64 + c16 * 8);
    }
}

// ---------------- kernel 3: mma.sync conv ----------------
__global__ void __launch_bounds__(256)
conv_mma_kernel(const float* __restrict__ bias, float* __restrict__ out) {
    extern __shared__ char smem[];
    const uint32_t sb = s2u(smem);
    const int tid = threadIdx.x, wid = tid >> 5, l = tid & 31;
    const int m0w = (wid & 1) * 64, n0w = (wid >> 1) * 32;
    const int bx = blockIdx.x;
    const int n = bx >> 7, h = bx & 127;

    const __nv_bfloat16* xhi = g_xhi + (size_t)n * (HH * WWID * C_IN);
    const __nv_bfloat16* xlo = g_xlo + (size_t)n * (HH * WWID * C_IN);

    float acc[4][4][4];
#pragma unroll
    for (int mi = 0; mi < 4; ++mi)
#pragma unroll
        for (int ni = 0; ni < 4; ++ni)
#pragma unroll
            for (int c = 0; c < 4; ++c) acc[mi][ni][c] = 0.f;

    // per-lane ldmatrix address bases
    const uint32_t arow = (uint32_t)(m0w + (l & 15) + 1) * A_STRIDE + (l >> 4) * 16;
    const uint32_t brow = (uint32_t)(n0w + ((l >> 4) << 3) + (l & 7)) * B_STRIDE
                        + ((l >> 3) & 1) * 16;

    // prologue: A(dh=-1, hi+lo) into pair 0, B(kpos 0)
    loadA(sb + 0 * A_BUF, xhi, h, -1, tid);
    loadA(sb + 1 * A_BUF, xlo, h, -1, tid);
    loadB(sb + SM_BOFF, 0, tid);
    CP_COMMIT();

#pragma unroll 1
    for (int it = 0; it < 9; ++it) {
        const int dh_i = it / 3;                // 0,1,2  (dh = dh_i - 1)
        const int dw   = it % 3 - 1;
        // prefetch next B; next-dh A pair on it%3==2
        if (it < 8) loadB(sb + SM_BOFF + ((it + 1) & 1) * B_BUF, it + 1, tid);
        if ((it % 3 == 2) && it < 8) {
            const int dhn = dh_i + 1, pn = dhn & 1;
            loadA(sb + (pn * 2 + 0) * A_BUF, xhi, h, dhn - 1, tid);
            loadA(sb + (pn * 2 + 1) * A_BUF, xlo, h, dhn - 1, tid);
        }
        CP_COMMIT();
        CP_WAIT1();
        __syncthreads();

        const int dhp = dh_i & 1;
        const uint32_t aB0 = sb + (dhp * 2 + 0) * A_BUF + arow + dw * A_STRIDE;
        const uint32_t aB1 = sb + (dhp * 2 + 1) * A_BUF + arow + dw * A_STRIDE;
        const uint32_t bB  = sb + SM_BOFF + (it & 1) * B_BUF + brow;

#pragma unroll
        for (int ks = 0; ks < 4; ++ks) {
            uint32_t b0[4], b1[4];
#pragma unroll
            for (int p2 = 0; p2 < 2; ++p2) {
                uint32_t r[4];
                ldsm4(r, bB + p2 * 16 * B_STRIDE + ks * 32);
                b0[p2 * 2]     = r[0]; b1[p2 * 2]     = r[1];
                b0[p2 * 2 + 1] = r[2]; b1[p2 * 2 + 1] = r[3];
            }
#pragma unroll
            for (int sp = 0; sp < 2; ++sp) {
                const uint32_t ab = sp ? aB1 : aB0;
                uint32_t a[4][4];
#pragma unroll
                for (int mi = 0; mi < 4; ++mi)
                    ldsm4(a[mi], ab + mi * 16 * A_STRIDE + ks * 32);
#pragma unroll
                for (int mi = 0; mi < 4; ++mi)
#pragma unroll
                    for (int ni = 0; ni < 4; ++ni)
                        mma16816(acc[mi][ni], a[mi], b0[ni], b1[ni]);
            }
        }
        __syncthreads();
    }

    // epilogue: +bias, ReLU, store
    float2 bb[4];
#pragma unroll
    for (int ni = 0; ni < 4; ++ni) {
        int col = n0w + ni * 8 + (l & 3) * 2;
        bb[ni] = *reinterpret_cast<const float2*>(bias + col);
    }
#pragma unroll
    for (int mi = 0; mi < 4; ++mi) {
#pragma unroll
        for (int ni = 0; ni < 4; ++ni) {
            int col = n0w + ni * 8 + (l & 3) * 2;
            size_t pix = (size_t)bx * 128 + m0w + mi * 16 + (l >> 2);
            float2 o0, o1;
            o0.x = fmaxf(acc[mi][ni][0] + bb[ni].x, 0.f);
            o0.y = fmaxf(acc[mi][ni][1] + bb[ni].y, 0.f);
            o1.x = fmaxf(acc[mi][ni][2] + bb[ni].x, 0.f);
            o1.y = fmaxf(acc[mi][ni][3] + bb[ni].y, 0.f);
            *reinterpret_cast<float2*>(out + pix * F_OUT + col) = o0;
            *reinterpret_cast<float2*>(out + (pix + 8) * F_OUT + col) = o1;
        }
    }
}

// ---------------- launch ----------------
extern "C" void kernel_launch(void* const* d_in, const int* in_sizes, int n_in,
                              void* d_out, int out_size) {
    const float* x    = (const float*)d_in[0];
    const float* kern = (const float*)d_in[1];
    const float* b    = (const float*)d_in[2];
    const float* D    = (const float*)d_in[3];
    const float* u    = (const float*)d_in[4];
    float* out = (float*)d_out;

    static int smem_set = 0;
    if (!smem_set) {
        cudaFuncSetAttribute(conv_mma_kernel,
                             cudaFuncAttributeMaxDynamicSharedMemorySize, SMEM_SZ);
        smem_set = 1;
    }

    weights_kernel<<<(F_OUT * C_IN + 255) / 256, 256>>>(D, u, kern);
    convert_kernel<<<(NPIX * C_IN / 4) / 256, 256>>>(x);
    conv_mma_kernel<<<NB * HH, 256, SMEM_SZ>>>(b, out);
}

// round 6
// speedup vs baseline: 6.4594x; 1.5278x over previous
#include <cuda_runtime.h>
#include <cuda_fp16.h>
#include <math_constants.h>
#include <cstdint>
#include <cstddef>

#define C_IN  64
#define F_OUT 128
#define NPOS  9
#define HH    128
#define WWID  128
#define NB    16
#define NPIX  (NB*HH*WWID)

__device__ __half g_xh[(size_t)NPIX * C_IN];
__device__ __half g_W[NPOS * F_OUT * C_IN];   // [kpos][f][c]

// ---------------- kernel 1: weights (blocks 0..31) + x->fp16 (rest) -------
__global__ void prep_kernel(const float* __restrict__ x,
                            const float* __restrict__ D,
                            const float* __restrict__ u,
                            const float* __restrict__ kern) {
    const int bx = blockIdx.x, tid = threadIdx.x;
    if (bx < 32) {
        int t = bx * 256 + tid;
        if (t >= F_OUT * C_IN) return;
        const float* Dp = D + t * NPOS;
        const float* up = u + t * NPOS;
        float pert[NPOS];
#pragma unroll
        for (int n = 0; n < NPOS; ++n) {
            float g = -0.001f * logf(-logf(up[n] + 1e-20f) + 1e-20f);
            pert[n] = Dp[n] + g;
        }
        unsigned sel = 0;
#pragma unroll
        for (int j = 0; j < 4; ++j) {
            int bi = 0; float bv = -CUDART_INF_F;
#pragma unroll
            for (int n = 0; n < NPOS; ++n) {
                bool tk = (sel >> n) & 1u;
                if (!tk && pert[n] > bv) { bv = pert[n]; bi = n; }
            }
            sel |= (1u << bi);
        }
        const float* kp = kern + t * NPOS;
#pragma unroll
        for (int n = 0; n < NPOS; ++n) {
            int p = t * NPOS + n;              // flat index in (3,3,64,128)
            float w = kp[n];
            float s = (w > 0.f) ? 1.f : ((w < 0.f) ? -1.f : 0.f);
            float v = ((sel >> n) & 1u) ? s : 0.f;
            int f = p & 127, c = (p >> 7) & 63, kpos = p >> 13;
            g_W[kpos * 8192 + f * 64 + c] = __float2half_rn(v);
        }
    } else {
        size_t i = (size_t)(bx - 32) * 256 + tid;     // float4 group
        float4 v = reinterpret_cast<const float4*>(x)[i];
        unsigned h0 = __half_as_ushort(__float2half_rn(v.x));
        unsigned h1 = __half_as_ushort(__float2half_rn(v.y));
        unsigned h2 = __half_as_ushort(__float2half_rn(v.z));
        unsigned h3 = __half_as_ushort(__float2half_rn(v.w));
        uint2 ph = make_uint2(h0 | (h1 << 16), h2 | (h3 << 16));
        reinterpret_cast<uint2*>(g_xh)[i] = ph;
    }
}

// ---------------- helpers ----------------
__device__ __forceinline__ uint32_t s2u(const void* p) {
    uint32_t a;
    asm("{ .reg .u64 t; cvta.to.shared.u64 t, %1; cvt.u32.u64 %0, t; }"
        : "=r"(a) : "l"(p));
    return a;
}
__device__ __forceinline__ void cpa16(uint32_t dst, const void* src) {
    asm volatile("cp.async.cg.shared.global [%0], [%1], 16;"
                 :: "r"(dst), "l"(src) : "memory");
}
#define CP_COMMIT() asm volatile("cp.async.commit_group;" ::: "memory")
#define CP_WAIT1()  asm volatile("cp.async.wait_group 1;" ::: "memory")

__device__ __forceinline__ void ldsm4(uint32_t* r, uint32_t addr) {
    asm volatile("ldmatrix.sync.aligned.m8n8.x4.shared.b16 {%0,%1,%2,%3}, [%4];"
                 : "=r"(r[0]), "=r"(r[1]), "=r"(r[2]), "=r"(r[3]) : "r"(addr));
}
__device__ __forceinline__ void mma16816(float* d, const uint32_t* a,
                                         uint32_t b0, uint32_t b1) {
    asm volatile(
        "mma.sync.aligned.m16n8k16.row.col.f32.f16.f16.f32 "
        "{%0,%1,%2,%3}, {%4,%5,%6,%7}, {%8,%9}, {%0,%1,%2,%3};"
        : "+f"(d[0]), "+f"(d[1]), "+f"(d[2]), "+f"(d[3])
        : "r"(a[0]), "r"(a[1]), "r"(a[2]), "r"(a[3]), "r"(b0), "r"(b1));
}

// smem layout
#define A_STRIDE 144                    // bytes per A row (64 fp16 + 16B pad)
#define A_ROWS   130                    // w_in -1..128 (rows 0,129 zero)
#define A_BUF    (A_ROWS * A_STRIDE)    // 18720
#define B_STRIDE 144
#define B_BUF    (128 * B_STRIDE)       // 18432
#define SM_BOFF  (2 * A_BUF)            // 37440
#define SMEM_SZ  (SM_BOFF + 2 * B_BUF)  // 74304

// Load A tile for dh: rows 1..128 <- w_in 0..127; rows 0,129 zeroed.
__device__ __forceinline__ void loadA(uint32_t abase, const __half* arr,
                                      int h, int dh, int tid) {
    const int hin = h + dh;
    if ((unsigned)hin < 128u) {
        if (tid < 18) {
            uint32_t adr = abase + ((tid < 9) ? 0u : (uint32_t)(129 * A_STRIDE))
                         + (uint32_t)(tid % 9) * 16u;
            asm volatile("st.shared.v4.b32 [%0], {%1,%1,%1,%1};"
                         :: "r"(adr), "r"(0) : "memory");
        }
        const __half* rowp = arr + (size_t)hin * (WWID * C_IN);
#pragma unroll
        for (int i = 0; i < 4; ++i) {
            int idx = i * 256 + tid;           // 0..1023
            int r = idx >> 3, c16 = idx & 7;
            cpa16(abase + (uint32_t)(r + 1) * A_STRIDE + c16 * 16,
                  rowp + r * C_IN + c16 * 8);
        }
    } else {
#pragma unroll
        for (int i = 0; i < 5; ++i) {
            int idx = i * 256 + tid;
            if (idx < (A_BUF / 16))
                asm volatile("st.shared.v4.b32 [%0], {%1,%1,%1,%1};"
                             :: "r"(abase + idx * 16), "r"(0) : "memory");
        }
    }
}
__device__ __forceinline__ void loadB(uint32_t bbase, int kpos, int tid) {
    const __half* w = g_W + kpos * 8192;
#pragma unroll
    for (int i = 0; i < 4; ++i) {
        int idx = i * 256 + tid;               // 0..1023
        int f = idx >> 3, c16 = idx & 7;
        cpa16(bbase + (uint32_t)f * B_STRIDE + c16 * 16, w + f * 64 + c16 * 8);
    }
}

// ---------------- kernel 2: mma.sync conv (single fp16 pass) --------------
__global__ void __launch_bounds__(256)
conv_mma_kernel(const float* __restrict__ bias, float* __restrict__ out) {
    extern __shared__ char smem[];
    const uint32_t sb = s2u(smem);
    const int tid = threadIdx.x, wid = tid >> 5, l = tid & 31;
    const int m0w = (wid & 1) * 64, n0w = (wid >> 1) * 32;
    const int bx = blockIdx.x;
    const int n = bx >> 7, h = bx & 127;

    const __half* xh = g_xh + (size_t)n * (HH * WWID * C_IN);

    float acc[4][4][4];
#pragma unroll
    for (int mi = 0; mi < 4; ++mi)
#pragma unroll
        for (int ni = 0; ni < 4; ++ni)
#pragma unroll
            for (int c = 0; c < 4; ++c) acc[mi][ni][c] = 0.f;

    const uint32_t arow = (uint32_t)(m0w + (l & 15) + 1) * A_STRIDE + (l >> 4) * 16;
    const uint32_t brow = (uint32_t)(n0w + ((l >> 4) << 3) + (l & 7)) * B_STRIDE
                        + ((l >> 3) & 1) * 16;

    // prologue: A(dh=-1) into buf 0, B(kpos 0)
    loadA(sb, xh, h, -1, tid);
    loadB(sb + SM_BOFF, 0, tid);
    CP_COMMIT();

#pragma unroll 1
    for (int it = 0; it < 9; ++it) {
        const int dh_i = it / 3;                // dh = dh_i - 1
        const int dw   = it % 3 - 1;
        if (it < 8) loadB(sb + SM_BOFF + ((it + 1) & 1) * B_BUF, it + 1, tid);
        if ((it % 3 == 2) && it < 8)
            loadA(sb + ((dh_i + 1) & 1) * A_BUF, xh, h, dh_i, tid);
        CP_COMMIT();
        CP_WAIT1();
        __syncthreads();

        const uint32_t aB = sb + (dh_i & 1) * A_BUF + arow + dw * A_STRIDE;
        const uint32_t bB = sb + SM_BOFF + (it & 1) * B_BUF + brow;

#pragma unroll
        for (int ks = 0; ks < 4; ++ks) {
            uint32_t b0[4], b1[4];
#pragma unroll
            for (int p2 = 0; p2 < 2; ++p2) {
                uint32_t r[4];
                ldsm4(r, bB + p2 * 16 * B_STRIDE + ks * 32);
                b0[p2 * 2]     = r[0]; b1[p2 * 2]     = r[1];
                b0[p2 * 2 + 1] = r[2]; b1[p2 * 2 + 1] = r[3];
            }
            uint32_t a[4][4];
#pragma unroll
            for (int mi = 0; mi < 4; ++mi)
                ldsm4(a[mi], aB + mi * 16 * A_STRIDE + ks * 32);
#pragma unroll
            for (int mi = 0; mi < 4; ++mi)
#pragma unroll
                for (int ni = 0; ni < 4; ++ni)
                    mma16816(acc[mi][ni], a[mi], b0[ni], b1[ni]);
        }
        __syncthreads();
    }

    // epilogue: +bias, ReLU, store
    float2 bb[4];
#pragma unroll
    for (int ni = 0; ni < 4; ++ni) {
        int col = n0w + ni * 8 + (l & 3) * 2;
        bb[ni] = *reinterpret_cast<const float2*>(bias + col);
    }
#pragma unroll
    for (int mi = 0; mi < 4; ++mi) {
#pragma unroll
        for (int ni = 0; ni < 4; ++ni) {
            int col = n0w + ni * 8 + (l & 3) * 2;
            size_t pix = (size_t)bx * 128 + m0w + mi * 16 + (l >> 2);
            float2 o0, o1;
            o0.x = fmaxf(acc[mi][ni][0] + bb[ni].x, 0.f);
            o0.y = fmaxf(acc[mi][ni][1] + bb[ni].y, 0.f);
            o1.x = fmaxf(acc[mi][ni][2] + bb[ni].x, 0.f);
            o1.y = fmaxf(acc[mi][ni][3] + bb[ni].y, 0.f);
            *reinterpret_cast<float2*>(out + pix * F_OUT + col) = o0;
            *reinterpret_cast<float2*>(out + (pix + 8) * F_OUT + col) = o1;
        }
    }
}

// ---------------- launch ----------------
extern "C" void kernel_launch(void* const* d_in, const int* in_sizes, int n_in,
                              void* d_out, int out_size) {
    const float* x    = (const float*)d_in[0];
    const float* kern = (const float*)d_in[1];
    const float* b    = (const float*)d_in[2];
    const float* D    = (const float*)d_in[3];
    const float* u    = (const float*)d_in[4];
    float* out = (float*)d_out;

    static int smem_set = 0;
    if (!smem_set) {
        cudaFuncSetAttribute(conv_mma_kernel,
                             cudaFuncAttributeMaxDynamicSharedMemorySize, SMEM_SZ);
        smem_set = 1;
    }

    prep_kernel<<<32 + (NPIX * C_IN / 4) / 256, 256>>>(x, D, u, kern);
    conv_mma_kernel<<<NB * HH, 256, SMEM_SZ>>>(b, out);
}